// round 12
// baseline (speedup 1.0000x reference)
#include <cuda_runtime.h>
#include <cuda_bf16.h>

#define FULLMASK 0xffffffffu
#define TT 4096

// ---- device scratch (allocation-free) ----
__device__ float g_p0[64][64];    // per-block feature col sum[32] + sumsq[32]
__device__ float g_p1[16][16];    // per-block h1 sum[8] + sumsq[8]
__device__ float g_p2[16][16];    // per-block h2 sum[8] + sumsq[8]
__device__ float g_h1[2048 * 8];
__device__ float g_h2[2048 * 8];

// ============ K1: bn0 column partial stats (64 x 256; 32 rows/block) ============
__global__ __launch_bounds__(256) void k_stats0(const float* __restrict__ features) {
    __shared__ float red[8][64];
    const int tid = threadIdx.x, warp = tid >> 5, lane = tid & 31;
    const float4* fp = (const float4*)(features + (size_t)blockIdx.x * 32 * 32);
    float4 v = __ldg(fp + tid);          // columns (tid%8)*4 .. +3
    float s0 = v.x, s1 = v.y, s2 = v.z, s3 = v.w;
    float q0 = v.x * v.x, q1 = v.y * v.y, q2 = v.z * v.z, q3 = v.w * v.w;
    #pragma unroll
    for (int d = 8; d <= 16; d <<= 1) {
        s0 += __shfl_xor_sync(FULLMASK, s0, d); s1 += __shfl_xor_sync(FULLMASK, s1, d);
        s2 += __shfl_xor_sync(FULLMASK, s2, d); s3 += __shfl_xor_sync(FULLMASK, s3, d);
        q0 += __shfl_xor_sync(FULLMASK, q0, d); q1 += __shfl_xor_sync(FULLMASK, q1, d);
        q2 += __shfl_xor_sync(FULLMASK, q2, d); q3 += __shfl_xor_sync(FULLMASK, q3, d);
    }
    if (lane < 8) {
        const int c = lane * 4;
        red[warp][c + 0] = s0; red[warp][c + 1] = s1;
        red[warp][c + 2] = s2; red[warp][c + 3] = s3;
        red[warp][32 + c + 0] = q0; red[warp][32 + c + 1] = q1;
        red[warp][32 + c + 2] = q2; red[warp][32 + c + 3] = q3;
    }
    __syncthreads();
    if (tid < 64) {
        float a = 0.f;
        #pragma unroll
        for (int w = 0; w < 8; w++) a += red[w][tid];
        g_p0[blockIdx.x][tid] = a;
    }
}

// ============ K2: finalize bn0, h1 = bn0(f) @ W1^T + b1, p1 partials (16 x 128) ============
__global__ __launch_bounds__(128) void k_h1(const float* __restrict__ features,
                                            const float* __restrict__ bn0_g,
                                            const float* __restrict__ bn0_b,
                                            const float* __restrict__ W1,
                                            const float* __restrict__ b1) {
    __shared__ float s_f[128][33];
    __shared__ float sW1[256], sb1[8];
    __shared__ float s_sc0[32], s_sh0[32];
    __shared__ float s_p[4][16];
    const int tid = threadIdx.x, warp = tid >> 5, lane = tid & 31;

    sW1[tid] = W1[tid];
    sW1[tid + 128] = W1[tid + 128];
    if (tid < 8) sb1[tid] = b1[tid];

    const float* fb = features + ((size_t)blockIdx.x * 128 + warp * 32) * 32;
    #pragma unroll 8
    for (int i = 0; i < 32; i++) s_f[warp * 32 + i][lane] = fb[i * 32 + lane];

    if (tid < 32) {
        float ss = 0.f, qq = 0.f;
        #pragma unroll 8
        for (int b = 0; b < 64; b++) { ss += g_p0[b][tid]; qq += g_p0[b][32 + tid]; }
        float mean = ss * (1.f / 2048.f);
        float var  = qq * (1.f / 2048.f) - mean * mean;
        float sc   = bn0_g[tid] * rsqrtf(var + 1e-5f);
        s_sc0[tid] = sc;
        s_sh0[tid] = bn0_b[tid] - mean * sc;
    }
    __syncthreads();

    float xn[32];
    #pragma unroll
    for (int c = 0; c < 32; c++) xn[c] = fmaf(s_f[tid][c], s_sc0[c], s_sh0[c]);
    float h[8];
    #pragma unroll
    for (int j = 0; j < 8; j++) {
        float a = sb1[j];
        #pragma unroll
        for (int c = 0; c < 32; c++) a = fmaf(sW1[j * 32 + c], xn[c], a);
        h[j] = a;
    }
    const int row = blockIdx.x * 128 + tid;
    float4* hp = (float4*)(g_h1 + row * 8);
    hp[0] = make_float4(h[0], h[1], h[2], h[3]);
    hp[1] = make_float4(h[4], h[5], h[6], h[7]);

    float sv[16];
    #pragma unroll
    for (int j = 0; j < 8; j++) { sv[j] = h[j]; sv[8 + j] = h[j] * h[j]; }
    #pragma unroll
    for (int d = 16; d; d >>= 1) {
        #pragma unroll
        for (int j = 0; j < 16; j++) sv[j] += __shfl_xor_sync(FULLMASK, sv[j], d);
    }
    if (lane < 16) s_p[warp][lane] = sv[lane];
    __syncthreads();
    if (tid < 16)
        g_p1[blockIdx.x][tid] = s_p[0][tid] + s_p[1][tid] + s_p[2][tid] + s_p[3][tid];
}

// ============ K3: finalize bn1, h2 = relu(bn1(h1)) @ W2^T + b2, p2 partials (16 x 128) ============
__global__ __launch_bounds__(128) void k_h2(const float* __restrict__ bn1_g,
                                            const float* __restrict__ bn1_b,
                                            const float* __restrict__ W2,
                                            const float* __restrict__ b2) {
    __shared__ float sW2[64], sb2[8];
    __shared__ float s_sc1[8], s_sh1[8];
    __shared__ float s_p[4][16];
    const int tid = threadIdx.x, warp = tid >> 5, lane = tid & 31;

    if (tid < 64) sW2[tid] = W2[tid];
    else if (tid < 72) sb2[tid - 64] = b2[tid - 64];
    if (tid < 8) {
        float ss = 0.f, qq = 0.f;
        #pragma unroll
        for (int b = 0; b < 16; b++) { ss += g_p1[b][tid]; qq += g_p1[b][8 + tid]; }
        float mean = ss * (1.f / 2048.f);
        float var  = qq * (1.f / 2048.f) - mean * mean;
        float sc   = bn1_g[tid] * rsqrtf(var + 1e-5f);
        s_sc1[tid] = sc;
        s_sh1[tid] = bn1_b[tid] - mean * sc;
    }
    __syncthreads();

    const int row = blockIdx.x * 128 + tid;
    const float4* hp = (const float4*)(g_h1 + row * 8);
    float4 v0 = hp[0], v1 = hp[1];
    float z[8] = {v0.x, v0.y, v0.z, v0.w, v1.x, v1.y, v1.z, v1.w};
    #pragma unroll
    for (int j = 0; j < 8; j++) z[j] = fmaxf(fmaf(z[j], s_sc1[j], s_sh1[j]), 0.f);
    float h[8];
    #pragma unroll
    for (int k = 0; k < 8; k++) {
        float a = sb2[k];
        #pragma unroll
        for (int j = 0; j < 8; j++) a = fmaf(sW2[k * 8 + j], z[j], a);
        h[k] = a;
    }
    float4* op = (float4*)(g_h2 + row * 8);
    op[0] = make_float4(h[0], h[1], h[2], h[3]);
    op[1] = make_float4(h[4], h[5], h[6], h[7]);

    float sv[16];
    #pragma unroll
    for (int j = 0; j < 8; j++) { sv[j] = h[j]; sv[8 + j] = h[j] * h[j]; }
    #pragma unroll
    for (int d = 16; d; d >>= 1) {
        #pragma unroll
        for (int j = 0; j < 16; j++) sv[j] += __shfl_xor_sync(FULLMASK, sv[j], d);
    }
    if (lane < 16) s_p[warp][lane] = sv[lane];
    __syncthreads();
    if (tid < 16)
        g_p2[blockIdx.x][tid] = s_p[0][tid] + s_p[1][tid] + s_p[2][tid] + s_p[3][tid];
}

// ============ K4: smem-staged scan (512 x 256; 4 rows x 2 warps; 64KB tile) ============
// Block stages its 4 rows (64 KB) once via coalesced cp.async with granule
// swizzle g ^ ((g>>4)&7), so the lane-strided float4 reads (stride 16 granules)
// are conflict-free LDS.128. Chunk c = half*32+lane covers steps [64c, 64c+64)
// in closed affine form; accumulators are affine in the chunk's entry state.
__global__ __launch_bounds__(256) void k_scan(const float* __restrict__ X,
                                              const float* __restrict__ Fp,
                                              const float* __restrict__ bn2_g,
                                              const float* __restrict__ bn2_b,
                                              const float* __restrict__ W3,
                                              const float* __restrict__ b3,
                                              const float* __restrict__ pn,
                                              float* __restrict__ out) {
    extern __shared__ float sx[];        // 4 * 4096 floats = 64 KB (swizzled)
    __shared__ float sW3[48], sb3[6], spn[6];
    __shared__ float s_sc2[8], s_sh2[8];
    __shared__ float s_T[4][4];
    __shared__ float s_red[8][2];

    const int tid  = threadIdx.x;
    const int warp = tid >> 5;
    const int lane = tid & 31;
    const int rowl = warp & 3;
    const int half = warp >> 2;
    const int row  = blockIdx.x * 4 + rowl;

    // ---- stage 4 rows: 4096 granules, 16/thread, coalesced src, swizzled dst ----
    {
        const float* src = X + (size_t)blockIdx.x * 4 * TT;
        const unsigned sb = (unsigned)__cvta_generic_to_shared(sx);
        #pragma unroll
        for (int k = 0; k < 16; k++) {
            unsigned gl  = (unsigned)(k * 256 + tid);
            unsigned rr  = gl >> 10;
            unsigned gr  = gl & 1023u;
            unsigned pos = gr ^ ((gr >> 4) & 7u);
            asm volatile("cp.async.cg.shared.global [%0], [%1], 16;"
                         :: "r"(sb + rr * 16384u + pos * 16u),
                            "l"(src + (size_t)gl * 4) : "memory");
        }
        asm volatile("cp.async.commit_group;" ::: "memory");
    }

    // ---- bn2 finalize + per-row params (overlaps the cp.async flight) ----
    if (tid < 48) sW3[tid] = W3[tid];
    else if (tid < 54) sb3[tid - 48] = b3[tid - 48];
    else if (tid < 60) spn[tid - 54] = pn[tid - 54];
    if (tid < 8) {
        float ss = 0.f, qq = 0.f;
        #pragma unroll
        for (int b = 0; b < 16; b++) { ss += g_p2[b][tid]; qq += g_p2[b][8 + tid]; }
        float mean = ss * (1.f / 2048.f);
        float var  = qq * (1.f / 2048.f) - mean * mean;
        float sc   = bn2_g[tid] * rsqrtf(var + 1e-5f);
        s_sc2[tid] = sc;
        s_sh2[tid] = bn2_b[tid] - mean * sc;
    }
    __syncthreads();

    const float4* hp = (const float4*)(g_h2 + row * 8);
    const float4 v0 = hp[0], v1 = hp[1];
    float z[8] = {v0.x, v0.y, v0.z, v0.w, v1.x, v1.y, v1.z, v1.w};
    #pragma unroll
    for (int j = 0; j < 8; j++) z[j] = fmaxf(fmaf(z[j], s_sc2[j], s_sh2[j]), 0.f);
    float sg[6];
    #pragma unroll
    for (int j = 0; j < 6; j++) {
        float a = sb3[j] + spn[j];
        #pragma unroll
        for (int k = 0; k < 8; k++) a = fmaf(sW3[j * 8 + k], z[k], a);
        sg[j] = __fdividef(1.f, 1.f + __expf(-a));
    }
    const float f_start = fmaf(4.5f,  sg[0], 0.5f);
    const float f_inf   = fmaf(0.49f, sg[1], 0.01f);
    const float f_decay = 2.f * sg[2];
    const float f_T     = 2.f * sg[3];
    const float w_off   = sg[4];
    const float w_T     = fmaf(0.49f, sg[5], 0.01f);

    const float df  = f_start - f_inf;
    const float lnD = fmaf(-2.30258509f, f_decay, -0.35667494f);  // ln(0.7*0.1^fd)
    const float H   = 10.f * __expf(-2.30258509f * f_T);          // 10*0.1^fT
    const float kf  = __fdividef(lnD, 4096.f * H);
    const float G   = __expf(kf);
    const float z0  = __fdividef(w_off, w_T);
    const float lw  = -__fdividef(1.f, 4096.f * w_T);
    const float R   = __expf(lw);
    const float cc  = 0.16228221f * __ldg(Fp);   // sqrt(2^(1/3)-1)*F/pi

    const int c  = half * 32 + lane;
    const int t0 = c << 6;
    float g = __expf(kf * (float)t0);
    float e = __expf(fmaf(lw, (float)t0, z0));   // may be inf -> w = 0 (correct)

    // ---- wait for staging, then scan out of smem ----
    asm volatile("cp.async.wait_group 0;" ::: "memory");
    __syncthreads();

    const float* xr = sx + rowl * 4096;
    const unsigned xorv = (unsigned)(c & 7);
    float xp;
    if (c == 0) {
        xp = xr[0];
    } else {
        const unsigned gp = (unsigned)(16 * c - 1);
        const unsigned pp = gp ^ ((gp >> 4) & 7u);
        xp = xr[pp * 4 + 3];
    }
    const float y0 = xr[0];

    float p = 1.f, r = 0.f, q1 = 0.f, q2 = 0.f;
    float a1 = 0.f, a2 = 0.f, bt = 0.f, ws = 0.f;

#define STEP(xval) do {                               \
    float w_ = __fdividef(1.f, 1.f + e);              \
    float f_ = fmaf(df, g, f_inf);                    \
    float i_ = __fdividef(1.f, cc + f_);              \
    float b_ = f_ * i_;                               \
    float ap = fmaf(-2.f, b_, 1.f);                   \
    g *= G; e *= R;                                   \
    float m_ = fmaf(b_, ap, b_);                      \
    float xx = (xval) + xp;                           \
    float u1 = b_ * xx;                               \
    float u2 = b_ * u1;                               \
    float pm = m_ * p;                                \
    float t2 = fmaf(m_, q1, u2);                      \
    p = ap * p;                                       \
    r = fmaf(ap, r, pm);                              \
    q1 = fmaf(ap, q1, u1);                            \
    q2 = fmaf(ap, q2, t2);                            \
    a1 = fmaf(w_, r, a1);                             \
    a2 = fmaf(w_, p, a2);                             \
    bt = fmaf(w_, q2, bt);                            \
    ws += w_;                                         \
    xp = (xval);                                      \
  } while (0)

    {
        const float4 v = *(const float4*)(xr + 4u * (16u * c + (0u ^ xorv)));
        if (c == 0) {
            // t = 0: y2_0 = y0 passes through identity -> a2 += w0, ws += w0
            float w0 = __fdividef(1.f, 1.f + e);
            a2 = w0; ws = w0;
            g *= G; e *= R;
            xp = v.x;                 // X[0] feeds the t=1 step
        } else {
            STEP(v.x);
        }
        STEP(v.y); STEP(v.z); STEP(v.w);
    }
    #pragma unroll 5
    for (unsigned j = 1; j < 16; j++) {
        const float4 v = *(const float4*)(xr + 4u * (16u * c + (j ^ xorv)));
        STEP(v.x); STEP(v.y); STEP(v.z); STEP(v.w);
    }
#undef STEP

    // intra-warp inclusive scan (compose self with prefix from lower lanes)
    #pragma unroll
    for (int d = 1; d < 32; d <<= 1) {
        float pL  = __shfl_up_sync(FULLMASK, p,  d);
        float rL  = __shfl_up_sync(FULLMASK, r,  d);
        float q1L = __shfl_up_sync(FULLMASK, q1, d);
        float q2L = __shfl_up_sync(FULLMASK, q2, d);
        if (lane >= d) {
            float pn2 = p * pL;
            float rn  = fmaf(r, pL, p * rL);
            float q1n = fmaf(p, q1L, q1);
            float q2n = fmaf(r, q1L, fmaf(p, q2L, q2));
            p = pn2; r = rn; q1 = q1n; q2 = q2n;
        }
    }
    // publish half-0 total (lane 31 inclusive) for half-1
    if (half == 0 && lane == 31) {
        s_T[rowl][0] = p; s_T[rowl][1] = r; s_T[rowl][2] = q1; s_T[rowl][3] = q2;
    }
    // exclusive shift (identity into lane 0)
    float pe  = __shfl_up_sync(FULLMASK, p,  1);
    float re  = __shfl_up_sync(FULLMASK, r,  1);
    float q1e = __shfl_up_sync(FULLMASK, q1, 1);
    float q2e = __shfl_up_sync(FULLMASK, q2, 1);
    if (lane == 0) { pe = 1.f; re = 0.f; q1e = 0.f; q2e = 0.f; }
    __syncthreads();
    if (half == 1) {   // compose exclusive prefix with half-0 total (applied first)
        const float pA  = s_T[rowl][0], rA  = s_T[rowl][1];
        const float q1A = s_T[rowl][2], q2A = s_T[rowl][3];
        float pn2 = pe * pA;
        float rn  = fmaf(re, pA, pe * rA);
        float q1n = fmaf(pe, q1A, q1e);
        float q2n = fmaf(re, q1A, fmaf(pe, q2A, q2e));
        pe = pn2; re = rn; q1e = q1n; q2e = q2n;
    }

    const float y1i = fmaf(pe, y0, q1e);
    const float y2i = fmaf(re + pe, y0, q2e);
    float contrib = fmaf(a1, y1i, fmaf(a2, y2i, bt));

    #pragma unroll
    for (int d = 16; d; d >>= 1) {
        contrib += __shfl_xor_sync(FULLMASK, contrib, d);
        ws      += __shfl_xor_sync(FULLMASK, ws, d);
    }
    if (lane == 0) { s_red[warp][0] = contrib; s_red[warp][1] = ws; }
    __syncthreads();
    if (half == 0 && lane == 0)
        out[row] = (s_red[warp][0] + s_red[warp + 4][0]) /
                   (s_red[warp][1] + s_red[warp + 4][1]);
}

extern "C" void kernel_launch(void* const* d_in, const int* in_sizes, int n_in,
                              void* d_out, int out_size) {
    const float* X        = (const float*)d_in[0];
    const float* features = (const float*)d_in[1];
    const float* F        = (const float*)d_in[2];
    const float* bn0_g    = (const float*)d_in[3];
    const float* bn0_b    = (const float*)d_in[4];
    const float* W1       = (const float*)d_in[5];
    const float* b1       = (const float*)d_in[6];
    const float* bn1_g    = (const float*)d_in[7];
    const float* bn1_b    = (const float*)d_in[8];
    const float* W2       = (const float*)d_in[9];
    const float* b2       = (const float*)d_in[10];
    const float* bn2_g    = (const float*)d_in[11];
    const float* bn2_b    = (const float*)d_in[12];
    const float* W3       = (const float*)d_in[13];
    const float* b3       = (const float*)d_in[14];
    const float* pn       = (const float*)d_in[15];
    float* out = (float*)d_out;

    const int dyn_smem = 4 * TT * sizeof(float);   // 64 KB
    cudaFuncSetAttribute(k_scan, cudaFuncAttributeMaxDynamicSharedMemorySize, dyn_smem);

    k_stats0<<<64, 256>>>(features);
    k_h1<<<16, 128>>>(features, bn0_g, bn0_b, W1, b1);
    k_h2<<<16, 128>>>(bn1_g, bn1_b, W2, b2);
    k_scan<<<512, 256, dyn_smem>>>(X, F, bn2_g, bn2_b, W3, b3, pn, out);
}